// round 12
// baseline (speedup 1.0000x reference)
#include <cuda_runtime.h>

// SphericalExpansion: per-edge radial×angular outer product scattered into
// out[idx_i, z[idx_j], n, m]  (20000, 4, 8, 16) fp32.
//
// Radial: RIln(d) = fc(d) * sum_k exp(-2(d-c_k)^2) * W[l*8+n,k] is smooth in d
// -> tabulated on a 2048-interval grid DIRECTLY IN SCATTER ORDER:
//    T4[j][pos] = ( R[lA,n0], R[lB,n0], R[lA,n0+4], R[lB,n0+4] )(d_j)
// so each lane's single LDG.128 yields exactly the 4 radial values its two
// output quads need. No shuffles, no bridge.
//
// Hot loop: 4 edges per warp-iter (2 independent pairs; halves h own an edge).
// Lane (h,pos) lerps its float4, computes its Y quad inline, commits 2x
// red.global.add.v4.f32 (quads pos and pos+16 of the 128-float segment).
// Prep kernel packs {x,y,z,d} per edge and rbase, and builds the table.

#define PI_F 3.14159265358979f
#define MAX_EDGES 800000
#define NKNOT 2048
#define DSCALE ((float)NKNOT / 5.0f)
#define DSTEP  (5.0f / (float)NKNOT)
#define TAB_N  ((NKNOT + 1) * 16)

__device__ int    g_rbase[MAX_EDGES];
__device__ float4 g_edge[MAX_EDGES];   // {x, y, z, d}
__device__ float4 g_tab4[TAB_N];       // [knot][pos] scatter-ordered radials

typedef unsigned long long u64_t;

__device__ __forceinline__ u64_t pack2(float lo, float hi) {
    u64_t r; asm("mov.b64 %0, {%1, %2};" : "=l"(r) : "f"(lo), "f"(hi)); return r;
}
__device__ __forceinline__ void unpack2(u64_t v, float& lo, float& hi) {
    asm("mov.b64 {%0, %1}, %2;" : "=f"(lo), "=f"(hi) : "l"(v));
}
__device__ __forceinline__ u64_t fma2(u64_t a, u64_t b, u64_t c) {
    u64_t d; asm("fma.rn.f32x2 %0, %1, %2, %3;" : "=l"(d) : "l"(a), "l"(b), "l"(c));
    return d;
}
__device__ __forceinline__ u64_t mul2(u64_t a, u64_t b) {
    u64_t d; asm("mul.rn.f32x2 %0, %1, %2;" : "=l"(d) : "l"(a), "l"(b));
    return d;
}
__device__ __forceinline__ void red_add_v4(float* p, float a, float b, float c, float d) {
    asm volatile("red.global.add.v4.f32 [%0], {%1,%2,%3,%4};"
                 :: "l"(p), "f"(a), "f"(b), "f"(c), "f"(d) : "memory");
}

// ---- fused prep: scatter-ordered radial table + edge packing + rbase ----
__global__ __launch_bounds__(512)
void prep_kernel(const float* __restrict__ W,
                 const float* __restrict__ dist,
                 const float* __restrict__ dirs,
                 const int*   __restrict__ idx_i,
                 const int*   __restrict__ idx_j,
                 const int*   __restrict__ zarr,
                 int n_edges)
{
    const int t  = blockIdx.x * blockDim.x + threadIdx.x;
    const int nt = gridDim.x * blockDim.x;

    if (t < TAB_N) {
        int j   = t >> 4;
        int pos = t & 15;
        int n0  = pos >> 2;
        int mq  = pos & 3;
        int lA  = (mq == 0) ? 0 : (mq == 3 ? 3 : 2);
        int lB  = (mq == 0) ? 1 : (mq == 1 ? 2 : 3);
        int rA0 = lA * 8 + n0,  rB0 = lB * 8 + n0;
        int rA1 = rA0 + 4,      rB1 = rB0 + 4;

        float d  = (float)j * DSTEP;
        float tt = fminf(fmaxf((d - 4.5f) * 2.0f, 0.0f), 1.0f);
        float fc = 0.5f * (cosf(tt * PI_F) + 1.0f);

        float sA0 = 0.f, sB0 = 0.f, sA1 = 0.f, sB1 = 0.f;
        #pragma unroll
        for (int k = 0; k < 16; ++k) {
            float ck = (float)k * (5.0f / 15.0f);
            float u  = d - ck;
            float g  = expf(-2.0f * u * u);
            sA0 = fmaf(g, W[rA0 * 16 + k], sA0);
            sB0 = fmaf(g, W[rB0 * 16 + k], sB0);
            sA1 = fmaf(g, W[rA1 * 16 + k], sA1);
            sB1 = fmaf(g, W[rB1 * 16 + k], sB1);
        }
        g_tab4[t] = make_float4(sA0 * fc, sB0 * fc, sA1 * fc, sB1 * fc);
    }

    for (int e = t; e < n_edges; e += nt) {
        g_rbase[e] = (idx_i[e] * 4 + zarr[idx_j[e]]) * 128;
        g_edge[e]  = make_float4(dirs[3 * e + 0], dirs[3 * e + 1],
                                 dirs[3 * e + 2], dist[e]);
    }
}

template <bool TAIL>
__global__ __launch_bounds__(256, 4)
void sph_expand_kernel(float* __restrict__ out, int n_edges)
{
    const int lane = threadIdx.x & 31;
    const int h    = lane >> 4;        // which edge of a pair
    const int pos  = lane & 15;
    const int mq   = pos & 3;

    const int gw = (blockIdx.x * blockDim.x + threadIdx.x) >> 5;
    const int nw = (gridDim.x * blockDim.x) >> 5;

    for (int e0 = 4 * gw; e0 < n_edges; e0 += 4 * nw) {
        int eA = e0 + h;
        int eB = e0 + 2 + h;
        bool vA = true, vB = true;
        if (TAIL) {
            vA = eA < n_edges; if (!vA) eA = n_edges - 1;
            vB = eB < n_edges; if (!vB) eB = n_edges - 1;
        }

        // ---------- batched loads ----------
        const int    rbA = g_rbase[eA];
        const float4 edA = g_edge[eA];
        const int    rbB = g_rbase[eB];
        const float4 edB = g_edge[eB];

        // ---------- radial lerp, pair A ----------
        float uA = edA.w * DSCALE;
        int   jA = __float2int_rd(uA);
        jA = min(max(jA, 0), NKNOT - 1);
        float fA = uA - (float)jA;
        const float4 a0 = g_tab4[jA * 16 + pos];
        const float4 a1 = g_tab4[(jA + 1) * 16 + pos];

        // ---------- radial lerp, pair B ----------
        float uB = edB.w * DSCALE;
        int   jB = __float2int_rd(uB);
        jB = min(max(jB, 0), NKNOT - 1);
        float fB = uB - (float)jB;
        const float4 b0 = g_tab4[jB * 16 + pos];
        const float4 b1 = g_tab4[(jB + 1) * 16 + pos];

        const u64_t fAp = pack2(fA, fA), gAp = pack2(1.0f - fA, 1.0f - fA);
        const u64_t fBp = pack2(fB, fB), gBp = pack2(1.0f - fB, 1.0f - fB);

        u64_t accA0 = fma2(pack2(a1.x, a1.y), fAp, mul2(pack2(a0.x, a0.y), gAp));
        u64_t accA1 = fma2(pack2(a1.z, a1.w), fAp, mul2(pack2(a0.z, a0.w), gAp));
        u64_t accB0 = fma2(pack2(b1.x, b1.y), fBp, mul2(pack2(b0.x, b0.y), gBp));
        u64_t accB1 = fma2(pack2(b1.z, b1.w), fBp, mul2(pack2(b0.z, b0.w), gBp));

        float aA0, aB0, aA1, aB1;   // pair A: quads pos / pos+16
        float bA0, bB0, bA1, bB1;   // pair B
        unpack2(accA0, aA0, aB0);
        unpack2(accA1, aA1, aB1);
        unpack2(accB0, bA0, bB0);
        unpack2(accB1, bA1, bB1);

        // ---------- Ylm + scatter, pair A ----------
        {
            const float x = edA.x, y = edA.y, zc = edA.z;
            const float x2 = x * x, y2 = y * y, z2 = zc * zc;
            const float Y0  = 0.28209479177387814f;
            const float Y1  = 0.4886025119029199f * y;
            const float Y2  = 0.4886025119029199f * zc;
            const float Y3  = 0.4886025119029199f * x;
            const float Y4  = 1.0925484305920792f * x * y;
            const float Y5  = 1.0925484305920792f * y * zc;
            const float Y6  = 0.31539156525252005f * (3.0f * z2 - 1.0f);
            const float Y7  = 1.0925484305920792f * x * zc;
            const float Y8  = 0.5462742152960396f * (x2 - y2);
            const float Y9  = 0.5900435899266435f * y * (3.0f * x2 - y2);
            const float Y10 = 2.890611442640554f  * x * y * zc;
            const float Y11 = 0.4570457994644658f * y * (5.0f * z2 - 1.0f);
            const float Y12 = 0.3731763325901154f * zc * (5.0f * z2 - 3.0f);
            const float Y13 = 0.4570457994644658f * x * (5.0f * z2 - 1.0f);
            const float Y14 = 1.445305721320277f  * zc * (x2 - y2);
            const float Y15 = 0.5900435899266435f * x * (x2 - 3.0f * y2);

            float s0, s1, s2, s3;
            if (mq == 0)      { s0 = Y0;  s1 = Y1;  s2 = Y2;  s3 = Y3;  }
            else if (mq == 1) { s0 = Y4;  s1 = Y5;  s2 = Y6;  s3 = Y7;  }
            else if (mq == 2) { s0 = Y8;  s1 = Y9;  s2 = Y10; s3 = Y11; }
            else              { s0 = Y12; s1 = Y13; s2 = Y14; s3 = Y15; }

            const size_t base = (size_t)rbA + (size_t)pos * 4;
            if (!TAIL || vA) {
                red_add_v4(out + base,      aA0 * s0, aB0 * s1, aB0 * s2, aB0 * s3);
                red_add_v4(out + base + 64, aA1 * s0, aB1 * s1, aB1 * s2, aB1 * s3);
            }
        }

        // ---------- Ylm + scatter, pair B ----------
        {
            const float x = edB.x, y = edB.y, zc = edB.z;
            const float x2 = x * x, y2 = y * y, z2 = zc * zc;
            const float Y0  = 0.28209479177387814f;
            const float Y1  = 0.4886025119029199f * y;
            const float Y2  = 0.4886025119029199f * zc;
            const float Y3  = 0.4886025119029199f * x;
            const float Y4  = 1.0925484305920792f * x * y;
            const float Y5  = 1.0925484305920792f * y * zc;
            const float Y6  = 0.31539156525252005f * (3.0f * z2 - 1.0f);
            const float Y7  = 1.0925484305920792f * x * zc;
            const float Y8  = 0.5462742152960396f * (x2 - y2);
            const float Y9  = 0.5900435899266435f * y * (3.0f * x2 - y2);
            const float Y10 = 2.890611442640554f  * x * y * zc;
            const float Y11 = 0.4570457994644658f * y * (5.0f * z2 - 1.0f);
            const float Y12 = 0.3731763325901154f * zc * (5.0f * z2 - 3.0f);
            const float Y13 = 0.4570457994644658f * x * (5.0f * z2 - 1.0f);
            const float Y14 = 1.445305721320277f  * zc * (x2 - y2);
            const float Y15 = 0.5900435899266435f * x * (x2 - 3.0f * y2);

            float s0, s1, s2, s3;
            if (mq == 0)      { s0 = Y0;  s1 = Y1;  s2 = Y2;  s3 = Y3;  }
            else if (mq == 1) { s0 = Y4;  s1 = Y5;  s2 = Y6;  s3 = Y7;  }
            else if (mq == 2) { s0 = Y8;  s1 = Y9;  s2 = Y10; s3 = Y11; }
            else              { s0 = Y12; s1 = Y13; s2 = Y14; s3 = Y15; }

            const size_t base = (size_t)rbB + (size_t)pos * 4;
            if (!TAIL || vB) {
                red_add_v4(out + base,      bA0 * s0, bB0 * s1, bB0 * s2, bB0 * s3);
                red_add_v4(out + base + 64, bA1 * s0, bB1 * s1, bB1 * s2, bB1 * s3);
            }
        }
    }
}

extern "C" void kernel_launch(void* const* d_in, const int* in_sizes, int n_in,
                              void* d_out, int out_size) {
    const float* dist = (const float*)d_in[0];
    const float* dirs = (const float*)d_in[1];
    const float* W    = (const float*)d_in[2];
    // d_in[3] = centers: analytic linspace(0, RC, 16)
    const int* z      = (const int*)d_in[4];
    const int* idx_i  = (const int*)d_in[5];
    const int* idx_j  = (const int*)d_in[6];
    int n_edges = in_sizes[0];
    if (n_edges > MAX_EDGES) n_edges = MAX_EDGES;   // scratch capacity (spec: 800000)

    cudaMemsetAsync(d_out, 0, (size_t)out_size * sizeof(float), 0);

    prep_kernel<<<(n_edges + 511) / 512, 512>>>(W, dist, dirs, idx_i, idx_j, z, n_edges);

    const int block = 256;
    const int grid  = 2368;    // 148 SMs x 16 blocks, grid-stride over 4-edge groups
    if ((n_edges & 3) == 0)
        sph_expand_kernel<false><<<grid, block>>>((float*)d_out, n_edges);
    else
        sph_expand_kernel<true><<<grid, block>>>((float*)d_out, n_edges);
}

// round 13
// speedup vs baseline: 1.0019x; 1.0019x over previous
#include <cuda_runtime.h>

// SphericalExpansion: per-edge radial×angular outer product scattered into
// out[idx_i, z[idx_j], n, m]  (20000, 4, 8, 16) fp32.
//
// Radial: RIln(d) = fc(d) * sum_k exp(-2(d-c_k)^2) * W[l*8+n,k] is smooth in d
// -> tabulated on a 2048-interval grid DIRECTLY IN SCATTER ORDER:
//    T4[j][pos] = ( R[lA,n0], R[lB,n0], R[lA,n0+4], R[lB,n0+4] )(d_j)
// so each lane's single LDG.128 yields exactly the 4 radial values its two
// output quads need. No shuffles, no bridge.
//
// Hot loop: 4 edges per warp-iter (2 independent pairs; halves h own an edge).
// Lane (h,pos) lerps its float4, computes its Y quad inline, commits 2x
// red.global.add.v4.f32 (quads pos and pos+16 of the 128-float segment).
// Prep kernel packs {x,y,z,d} per edge and rbase, and builds the table.

#define PI_F 3.14159265358979f
#define MAX_EDGES 800000
#define NKNOT 2048
#define DSCALE ((float)NKNOT / 5.0f)
#define DSTEP  (5.0f / (float)NKNOT)
#define TAB_N  ((NKNOT + 1) * 16)

__device__ int    g_rbase[MAX_EDGES];
__device__ float4 g_edge[MAX_EDGES];   // {x, y, z, d}
__device__ float4 g_tab4[TAB_N];       // [knot][pos] scatter-ordered radials

typedef unsigned long long u64_t;

__device__ __forceinline__ u64_t pack2(float lo, float hi) {
    u64_t r; asm("mov.b64 %0, {%1, %2};" : "=l"(r) : "f"(lo), "f"(hi)); return r;
}
__device__ __forceinline__ void unpack2(u64_t v, float& lo, float& hi) {
    asm("mov.b64 {%0, %1}, %2;" : "=f"(lo), "=f"(hi) : "l"(v));
}
__device__ __forceinline__ u64_t fma2(u64_t a, u64_t b, u64_t c) {
    u64_t d; asm("fma.rn.f32x2 %0, %1, %2, %3;" : "=l"(d) : "l"(a), "l"(b), "l"(c));
    return d;
}
__device__ __forceinline__ u64_t mul2(u64_t a, u64_t b) {
    u64_t d; asm("mul.rn.f32x2 %0, %1, %2;" : "=l"(d) : "l"(a), "l"(b));
    return d;
}
__device__ __forceinline__ void red_add_v4(float* p, float a, float b, float c, float d) {
    asm volatile("red.global.add.v4.f32 [%0], {%1,%2,%3,%4};"
                 :: "l"(p), "f"(a), "f"(b), "f"(c), "f"(d) : "memory");
}

// ---- fused prep: scatter-ordered radial table + edge packing + rbase ----
__global__ __launch_bounds__(512)
void prep_kernel(const float* __restrict__ W,
                 const float* __restrict__ dist,
                 const float* __restrict__ dirs,
                 const int*   __restrict__ idx_i,
                 const int*   __restrict__ idx_j,
                 const int*   __restrict__ zarr,
                 int n_edges)
{
    const int t  = blockIdx.x * blockDim.x + threadIdx.x;
    const int nt = gridDim.x * blockDim.x;

    if (t < TAB_N) {
        int j   = t >> 4;
        int pos = t & 15;
        int n0  = pos >> 2;
        int mq  = pos & 3;
        int lA  = (mq == 0) ? 0 : (mq == 3 ? 3 : 2);
        int lB  = (mq == 0) ? 1 : (mq == 1 ? 2 : 3);
        int rA0 = lA * 8 + n0,  rB0 = lB * 8 + n0;
        int rA1 = rA0 + 4,      rB1 = rB0 + 4;

        float d  = (float)j * DSTEP;
        float tt = fminf(fmaxf((d - 4.5f) * 2.0f, 0.0f), 1.0f);
        float fc = 0.5f * (cosf(tt * PI_F) + 1.0f);

        float sA0 = 0.f, sB0 = 0.f, sA1 = 0.f, sB1 = 0.f;
        #pragma unroll
        for (int k = 0; k < 16; ++k) {
            float ck = (float)k * (5.0f / 15.0f);
            float u  = d - ck;
            float g  = expf(-2.0f * u * u);
            sA0 = fmaf(g, W[rA0 * 16 + k], sA0);
            sB0 = fmaf(g, W[rB0 * 16 + k], sB0);
            sA1 = fmaf(g, W[rA1 * 16 + k], sA1);
            sB1 = fmaf(g, W[rB1 * 16 + k], sB1);
        }
        g_tab4[t] = make_float4(sA0 * fc, sB0 * fc, sA1 * fc, sB1 * fc);
    }

    for (int e = t; e < n_edges; e += nt) {
        g_rbase[e] = (idx_i[e] * 4 + zarr[idx_j[e]]) * 128;
        g_edge[e]  = make_float4(dirs[3 * e + 0], dirs[3 * e + 1],
                                 dirs[3 * e + 2], dist[e]);
    }
}

template <bool TAIL>
__global__ __launch_bounds__(256, 4)
void sph_expand_kernel(float* __restrict__ out, int n_edges)
{
    const int lane = threadIdx.x & 31;
    const int h    = lane >> 4;        // which edge of a pair
    const int pos  = lane & 15;
    const int mq   = pos & 3;

    const int gw = (blockIdx.x * blockDim.x + threadIdx.x) >> 5;
    const int nw = (gridDim.x * blockDim.x) >> 5;

    for (int e0 = 4 * gw; e0 < n_edges; e0 += 4 * nw) {
        int eA = e0 + h;
        int eB = e0 + 2 + h;
        bool vA = true, vB = true;
        if (TAIL) {
            vA = eA < n_edges; if (!vA) eA = n_edges - 1;
            vB = eB < n_edges; if (!vB) eB = n_edges - 1;
        }

        // ---------- batched loads ----------
        const int    rbA = g_rbase[eA];
        const float4 edA = g_edge[eA];
        const int    rbB = g_rbase[eB];
        const float4 edB = g_edge[eB];

        // ---------- radial lerp, pair A ----------
        float uA = edA.w * DSCALE;
        int   jA = __float2int_rd(uA);
        jA = min(max(jA, 0), NKNOT - 1);
        float fA = uA - (float)jA;
        const float4 a0 = g_tab4[jA * 16 + pos];
        const float4 a1 = g_tab4[(jA + 1) * 16 + pos];

        // ---------- radial lerp, pair B ----------
        float uB = edB.w * DSCALE;
        int   jB = __float2int_rd(uB);
        jB = min(max(jB, 0), NKNOT - 1);
        float fB = uB - (float)jB;
        const float4 b0 = g_tab4[jB * 16 + pos];
        const float4 b1 = g_tab4[(jB + 1) * 16 + pos];

        const u64_t fAp = pack2(fA, fA), gAp = pack2(1.0f - fA, 1.0f - fA);
        const u64_t fBp = pack2(fB, fB), gBp = pack2(1.0f - fB, 1.0f - fB);

        u64_t accA0 = fma2(pack2(a1.x, a1.y), fAp, mul2(pack2(a0.x, a0.y), gAp));
        u64_t accA1 = fma2(pack2(a1.z, a1.w), fAp, mul2(pack2(a0.z, a0.w), gAp));
        u64_t accB0 = fma2(pack2(b1.x, b1.y), fBp, mul2(pack2(b0.x, b0.y), gBp));
        u64_t accB1 = fma2(pack2(b1.z, b1.w), fBp, mul2(pack2(b0.z, b0.w), gBp));

        float aA0, aB0, aA1, aB1;   // pair A: quads pos / pos+16
        float bA0, bB0, bA1, bB1;   // pair B
        unpack2(accA0, aA0, aB0);
        unpack2(accA1, aA1, aB1);
        unpack2(accB0, bA0, bB0);
        unpack2(accB1, bA1, bB1);

        // ---------- Ylm + scatter, pair A ----------
        {
            const float x = edA.x, y = edA.y, zc = edA.z;
            const float x2 = x * x, y2 = y * y, z2 = zc * zc;
            const float Y0  = 0.28209479177387814f;
            const float Y1  = 0.4886025119029199f * y;
            const float Y2  = 0.4886025119029199f * zc;
            const float Y3  = 0.4886025119029199f * x;
            const float Y4  = 1.0925484305920792f * x * y;
            const float Y5  = 1.0925484305920792f * y * zc;
            const float Y6  = 0.31539156525252005f * (3.0f * z2 - 1.0f);
            const float Y7  = 1.0925484305920792f * x * zc;
            const float Y8  = 0.5462742152960396f * (x2 - y2);
            const float Y9  = 0.5900435899266435f * y * (3.0f * x2 - y2);
            const float Y10 = 2.890611442640554f  * x * y * zc;
            const float Y11 = 0.4570457994644658f * y * (5.0f * z2 - 1.0f);
            const float Y12 = 0.3731763325901154f * zc * (5.0f * z2 - 3.0f);
            const float Y13 = 0.4570457994644658f * x * (5.0f * z2 - 1.0f);
            const float Y14 = 1.445305721320277f  * zc * (x2 - y2);
            const float Y15 = 0.5900435899266435f * x * (x2 - 3.0f * y2);

            float s0, s1, s2, s3;
            if (mq == 0)      { s0 = Y0;  s1 = Y1;  s2 = Y2;  s3 = Y3;  }
            else if (mq == 1) { s0 = Y4;  s1 = Y5;  s2 = Y6;  s3 = Y7;  }
            else if (mq == 2) { s0 = Y8;  s1 = Y9;  s2 = Y10; s3 = Y11; }
            else              { s0 = Y12; s1 = Y13; s2 = Y14; s3 = Y15; }

            const size_t base = (size_t)rbA + (size_t)pos * 4;
            if (!TAIL || vA) {
                red_add_v4(out + base,      aA0 * s0, aB0 * s1, aB0 * s2, aB0 * s3);
                red_add_v4(out + base + 64, aA1 * s0, aB1 * s1, aB1 * s2, aB1 * s3);
            }
        }

        // ---------- Ylm + scatter, pair B ----------
        {
            const float x = edB.x, y = edB.y, zc = edB.z;
            const float x2 = x * x, y2 = y * y, z2 = zc * zc;
            const float Y0  = 0.28209479177387814f;
            const float Y1  = 0.4886025119029199f * y;
            const float Y2  = 0.4886025119029199f * zc;
            const float Y3  = 0.4886025119029199f * x;
            const float Y4  = 1.0925484305920792f * x * y;
            const float Y5  = 1.0925484305920792f * y * zc;
            const float Y6  = 0.31539156525252005f * (3.0f * z2 - 1.0f);
            const float Y7  = 1.0925484305920792f * x * zc;
            const float Y8  = 0.5462742152960396f * (x2 - y2);
            const float Y9  = 0.5900435899266435f * y * (3.0f * x2 - y2);
            const float Y10 = 2.890611442640554f  * x * y * zc;
            const float Y11 = 0.4570457994644658f * y * (5.0f * z2 - 1.0f);
            const float Y12 = 0.3731763325901154f * zc * (5.0f * z2 - 3.0f);
            const float Y13 = 0.4570457994644658f * x * (5.0f * z2 - 1.0f);
            const float Y14 = 1.445305721320277f  * zc * (x2 - y2);
            const float Y15 = 0.5900435899266435f * x * (x2 - 3.0f * y2);

            float s0, s1, s2, s3;
            if (mq == 0)      { s0 = Y0;  s1 = Y1;  s2 = Y2;  s3 = Y3;  }
            else if (mq == 1) { s0 = Y4;  s1 = Y5;  s2 = Y6;  s3 = Y7;  }
            else if (mq == 2) { s0 = Y8;  s1 = Y9;  s2 = Y10; s3 = Y11; }
            else              { s0 = Y12; s1 = Y13; s2 = Y14; s3 = Y15; }

            const size_t base = (size_t)rbB + (size_t)pos * 4;
            if (!TAIL || vB) {
                red_add_v4(out + base,      bA0 * s0, bB0 * s1, bB0 * s2, bB0 * s3);
                red_add_v4(out + base + 64, bA1 * s0, bB1 * s1, bB1 * s2, bB1 * s3);
            }
        }
    }
}

extern "C" void kernel_launch(void* const* d_in, const int* in_sizes, int n_in,
                              void* d_out, int out_size) {
    const float* dist = (const float*)d_in[0];
    const float* dirs = (const float*)d_in[1];
    const float* W    = (const float*)d_in[2];
    // d_in[3] = centers: analytic linspace(0, RC, 16)
    const int* z      = (const int*)d_in[4];
    const int* idx_i  = (const int*)d_in[5];
    const int* idx_j  = (const int*)d_in[6];
    int n_edges = in_sizes[0];
    if (n_edges > MAX_EDGES) n_edges = MAX_EDGES;   // scratch capacity (spec: 800000)

    cudaMemsetAsync(d_out, 0, (size_t)out_size * sizeof(float), 0);

    prep_kernel<<<(n_edges + 511) / 512, 512>>>(W, dist, dirs, idx_i, idx_j, z, n_edges);

    const int block = 256;
    const int grid  = 2368;    // 148 SMs x 16 blocks, grid-stride over 4-edge groups
    if ((n_edges & 3) == 0)
        sph_expand_kernel<false><<<grid, block>>>((float*)d_out, n_edges);
    else
        sph_expand_kernel<true><<<grid, block>>>((float*)d_out, n_edges);
}

// round 14
// speedup vs baseline: 1.0182x; 1.0163x over previous
#include <cuda_runtime.h>

// SphericalExpansion: per-edge radial×angular outer product scattered into
// out[idx_i, z[idx_j], n, m]  (20000, 4, 8, 16) fp32.
//
// Radial: RIln(d) = fc(d) * sum_k exp(-2(d-c_k)^2) * W[l*8+n,k] is smooth in d
// -> tabulated on a 2048-interval grid DIRECTLY IN SCATTER ORDER:
//    T4[j][pos] = ( R[lA,n0], R[lB,n0], R[lA,n0+4], R[lB,n0+4] )(d_j)
// so each lane's single LDG.128 yields exactly the 4 radial values its two
// output quads need. No shuffles, no bridge.
//
// Hot loop: 4 edges per warp-iter (2 independent pairs; halves h own an edge).
// Lane (h,pos) lerps its float4, computes its Y quad inline, commits 2x
// red.global.add.v4.f32 (quads pos and pos+16 of the 128-float segment).
// Prep kernel packs {x,y,z,d} per edge and rbase, and builds the table.

#define PI_F 3.14159265358979f
#define MAX_EDGES 800000
#define NKNOT 2048
#define DSCALE ((float)NKNOT / 5.0f)
#define DSTEP  (5.0f / (float)NKNOT)
#define TAB_N  ((NKNOT + 1) * 16)

__device__ int    g_rbase[MAX_EDGES];
__device__ float4 g_edge[MAX_EDGES];   // {x, y, z, d}
__device__ float4 g_tab4[TAB_N];       // [knot][pos] scatter-ordered radials

typedef unsigned long long u64_t;

__device__ __forceinline__ u64_t pack2(float lo, float hi) {
    u64_t r; asm("mov.b64 %0, {%1, %2};" : "=l"(r) : "f"(lo), "f"(hi)); return r;
}
__device__ __forceinline__ void unpack2(u64_t v, float& lo, float& hi) {
    asm("mov.b64 {%0, %1}, %2;" : "=f"(lo), "=f"(hi) : "l"(v));
}
__device__ __forceinline__ u64_t fma2(u64_t a, u64_t b, u64_t c) {
    u64_t d; asm("fma.rn.f32x2 %0, %1, %2, %3;" : "=l"(d) : "l"(a), "l"(b), "l"(c));
    return d;
}
__device__ __forceinline__ u64_t mul2(u64_t a, u64_t b) {
    u64_t d; asm("mul.rn.f32x2 %0, %1, %2;" : "=l"(d) : "l"(a), "l"(b));
    return d;
}
__device__ __forceinline__ void red_add_v4(float* p, float a, float b, float c, float d) {
    asm volatile("red.global.add.v4.f32 [%0], {%1,%2,%3,%4};"
                 :: "l"(p), "f"(a), "f"(b), "f"(c), "f"(d) : "memory");
}

// ---- fused prep: scatter-ordered radial table + edge packing + rbase ----
__global__ __launch_bounds__(512)
void prep_kernel(const float* __restrict__ W,
                 const float* __restrict__ dist,
                 const float* __restrict__ dirs,
                 const int*   __restrict__ idx_i,
                 const int*   __restrict__ idx_j,
                 const int*   __restrict__ zarr,
                 int n_edges)
{
    const int t  = blockIdx.x * blockDim.x + threadIdx.x;
    const int nt = gridDim.x * blockDim.x;

    if (t < TAB_N) {
        int j   = t >> 4;
        int pos = t & 15;
        int n0  = pos >> 2;
        int mq  = pos & 3;
        int lA  = (mq == 0) ? 0 : (mq == 3 ? 3 : 2);
        int lB  = (mq == 0) ? 1 : (mq == 1 ? 2 : 3);
        int rA0 = lA * 8 + n0,  rB0 = lB * 8 + n0;
        int rA1 = rA0 + 4,      rB1 = rB0 + 4;

        float d  = (float)j * DSTEP;
        float tt = fminf(fmaxf((d - 4.5f) * 2.0f, 0.0f), 1.0f);
        float fc = 0.5f * (cosf(tt * PI_F) + 1.0f);

        float sA0 = 0.f, sB0 = 0.f, sA1 = 0.f, sB1 = 0.f;
        #pragma unroll
        for (int k = 0; k < 16; ++k) {
            float ck = (float)k * (5.0f / 15.0f);
            float u  = d - ck;
            float g  = expf(-2.0f * u * u);
            sA0 = fmaf(g, W[rA0 * 16 + k], sA0);
            sB0 = fmaf(g, W[rB0 * 16 + k], sB0);
            sA1 = fmaf(g, W[rA1 * 16 + k], sA1);
            sB1 = fmaf(g, W[rB1 * 16 + k], sB1);
        }
        g_tab4[t] = make_float4(sA0 * fc, sB0 * fc, sA1 * fc, sB1 * fc);
    }

    for (int e = t; e < n_edges; e += nt) {
        g_rbase[e] = (idx_i[e] * 4 + zarr[idx_j[e]]) * 128;
        g_edge[e]  = make_float4(dirs[3 * e + 0], dirs[3 * e + 1],
                                 dirs[3 * e + 2], dist[e]);
    }
}

template <bool TAIL>
__global__ __launch_bounds__(256, 4)
void sph_expand_kernel(float* __restrict__ out, int n_edges)
{
    const int lane = threadIdx.x & 31;
    const int h    = lane >> 4;        // which edge of a pair
    const int pos  = lane & 15;
    const int mq   = pos & 3;

    const int gw = (blockIdx.x * blockDim.x + threadIdx.x) >> 5;
    const int nw = (gridDim.x * blockDim.x) >> 5;

    for (int e0 = 4 * gw; e0 < n_edges; e0 += 4 * nw) {
        int eA = e0 + h;
        int eB = e0 + 2 + h;
        bool vA = true, vB = true;
        if (TAIL) {
            vA = eA < n_edges; if (!vA) eA = n_edges - 1;
            vB = eB < n_edges; if (!vB) eB = n_edges - 1;
        }

        // ---------- batched loads ----------
        const int    rbA = g_rbase[eA];
        const float4 edA = g_edge[eA];
        const int    rbB = g_rbase[eB];
        const float4 edB = g_edge[eB];

        // ---------- radial lerp, pair A ----------
        float uA = edA.w * DSCALE;
        int   jA = __float2int_rd(uA);
        jA = min(max(jA, 0), NKNOT - 1);
        float fA = uA - (float)jA;
        const float4 a0 = g_tab4[jA * 16 + pos];
        const float4 a1 = g_tab4[(jA + 1) * 16 + pos];

        // ---------- radial lerp, pair B ----------
        float uB = edB.w * DSCALE;
        int   jB = __float2int_rd(uB);
        jB = min(max(jB, 0), NKNOT - 1);
        float fB = uB - (float)jB;
        const float4 b0 = g_tab4[jB * 16 + pos];
        const float4 b1 = g_tab4[(jB + 1) * 16 + pos];

        const u64_t fAp = pack2(fA, fA), gAp = pack2(1.0f - fA, 1.0f - fA);
        const u64_t fBp = pack2(fB, fB), gBp = pack2(1.0f - fB, 1.0f - fB);

        u64_t accA0 = fma2(pack2(a1.x, a1.y), fAp, mul2(pack2(a0.x, a0.y), gAp));
        u64_t accA1 = fma2(pack2(a1.z, a1.w), fAp, mul2(pack2(a0.z, a0.w), gAp));
        u64_t accB0 = fma2(pack2(b1.x, b1.y), fBp, mul2(pack2(b0.x, b0.y), gBp));
        u64_t accB1 = fma2(pack2(b1.z, b1.w), fBp, mul2(pack2(b0.z, b0.w), gBp));

        float aA0, aB0, aA1, aB1;   // pair A: quads pos / pos+16
        float bA0, bB0, bA1, bB1;   // pair B
        unpack2(accA0, aA0, aB0);
        unpack2(accA1, aA1, aB1);
        unpack2(accB0, bA0, bB0);
        unpack2(accB1, bA1, bB1);

        // ---------- Ylm + scatter, pair A ----------
        {
            const float x = edA.x, y = edA.y, zc = edA.z;
            const float x2 = x * x, y2 = y * y, z2 = zc * zc;
            const float Y0  = 0.28209479177387814f;
            const float Y1  = 0.4886025119029199f * y;
            const float Y2  = 0.4886025119029199f * zc;
            const float Y3  = 0.4886025119029199f * x;
            const float Y4  = 1.0925484305920792f * x * y;
            const float Y5  = 1.0925484305920792f * y * zc;
            const float Y6  = 0.31539156525252005f * (3.0f * z2 - 1.0f);
            const float Y7  = 1.0925484305920792f * x * zc;
            const float Y8  = 0.5462742152960396f * (x2 - y2);
            const float Y9  = 0.5900435899266435f * y * (3.0f * x2 - y2);
            const float Y10 = 2.890611442640554f  * x * y * zc;
            const float Y11 = 0.4570457994644658f * y * (5.0f * z2 - 1.0f);
            const float Y12 = 0.3731763325901154f * zc * (5.0f * z2 - 3.0f);
            const float Y13 = 0.4570457994644658f * x * (5.0f * z2 - 1.0f);
            const float Y14 = 1.445305721320277f  * zc * (x2 - y2);
            const float Y15 = 0.5900435899266435f * x * (x2 - 3.0f * y2);

            float s0, s1, s2, s3;
            if (mq == 0)      { s0 = Y0;  s1 = Y1;  s2 = Y2;  s3 = Y3;  }
            else if (mq == 1) { s0 = Y4;  s1 = Y5;  s2 = Y6;  s3 = Y7;  }
            else if (mq == 2) { s0 = Y8;  s1 = Y9;  s2 = Y10; s3 = Y11; }
            else              { s0 = Y12; s1 = Y13; s2 = Y14; s3 = Y15; }

            const size_t base = (size_t)rbA + (size_t)pos * 4;
            if (!TAIL || vA) {
                red_add_v4(out + base,      aA0 * s0, aB0 * s1, aB0 * s2, aB0 * s3);
                red_add_v4(out + base + 64, aA1 * s0, aB1 * s1, aB1 * s2, aB1 * s3);
            }
        }

        // ---------- Ylm + scatter, pair B ----------
        {
            const float x = edB.x, y = edB.y, zc = edB.z;
            const float x2 = x * x, y2 = y * y, z2 = zc * zc;
            const float Y0  = 0.28209479177387814f;
            const float Y1  = 0.4886025119029199f * y;
            const float Y2  = 0.4886025119029199f * zc;
            const float Y3  = 0.4886025119029199f * x;
            const float Y4  = 1.0925484305920792f * x * y;
            const float Y5  = 1.0925484305920792f * y * zc;
            const float Y6  = 0.31539156525252005f * (3.0f * z2 - 1.0f);
            const float Y7  = 1.0925484305920792f * x * zc;
            const float Y8  = 0.5462742152960396f * (x2 - y2);
            const float Y9  = 0.5900435899266435f * y * (3.0f * x2 - y2);
            const float Y10 = 2.890611442640554f  * x * y * zc;
            const float Y11 = 0.4570457994644658f * y * (5.0f * z2 - 1.0f);
            const float Y12 = 0.3731763325901154f * zc * (5.0f * z2 - 3.0f);
            const float Y13 = 0.4570457994644658f * x * (5.0f * z2 - 1.0f);
            const float Y14 = 1.445305721320277f  * zc * (x2 - y2);
            const float Y15 = 0.5900435899266435f * x * (x2 - 3.0f * y2);

            float s0, s1, s2, s3;
            if (mq == 0)      { s0 = Y0;  s1 = Y1;  s2 = Y2;  s3 = Y3;  }
            else if (mq == 1) { s0 = Y4;  s1 = Y5;  s2 = Y6;  s3 = Y7;  }
            else if (mq == 2) { s0 = Y8;  s1 = Y9;  s2 = Y10; s3 = Y11; }
            else              { s0 = Y12; s1 = Y13; s2 = Y14; s3 = Y15; }

            const size_t base = (size_t)rbB + (size_t)pos * 4;
            if (!TAIL || vB) {
                red_add_v4(out + base,      bA0 * s0, bB0 * s1, bB0 * s2, bB0 * s3);
                red_add_v4(out + base + 64, bA1 * s0, bB1 * s1, bB1 * s2, bB1 * s3);
            }
        }
    }
}

extern "C" void kernel_launch(void* const* d_in, const int* in_sizes, int n_in,
                              void* d_out, int out_size) {
    const float* dist = (const float*)d_in[0];
    const float* dirs = (const float*)d_in[1];
    const float* W    = (const float*)d_in[2];
    // d_in[3] = centers: analytic linspace(0, RC, 16)
    const int* z      = (const int*)d_in[4];
    const int* idx_i  = (const int*)d_in[5];
    const int* idx_j  = (const int*)d_in[6];
    int n_edges = in_sizes[0];
    if (n_edges > MAX_EDGES) n_edges = MAX_EDGES;   // scratch capacity (spec: 800000)

    cudaMemsetAsync(d_out, 0, (size_t)out_size * sizeof(float), 0);

    prep_kernel<<<(n_edges + 511) / 512, 512>>>(W, dist, dirs, idx_i, idx_j, z, n_edges);

    const int block = 256;
    const int grid  = 2368;    // 148 SMs x 16 blocks, grid-stride over 4-edge groups
    if ((n_edges & 3) == 0)
        sph_expand_kernel<false><<<grid, block>>>((float*)d_out, n_edges);
    else
        sph_expand_kernel<true><<<grid, block>>>((float*)d_out, n_edges);
}